// round 4
// baseline (speedup 1.0000x reference)
#include <cuda_runtime.h>
#include <cuda_bf16.h>

// ButterflyTransform: 12 layers of adjacent-pair 2x2 butterflies over [8192, 4096].
// All layers pair the SAME adjacent elements (2p, 2p+1), so the whole network
// collapses to one composite 2x2 matrix per pair:
//   M_p = W0[p] @ W1[p] @ ... @ W11[p]
// and a single bandwidth-bound apply pass: out[b,2p:2p+2] = x[b,2p:2p+2] @ M_p.

#define N_SIZE   4096
#define N_HALF   2048
#define LOG_N    12
#define N_BATCH  8192

// Scratch for composite matrices: 2048 pairs x (m00,m01,m10,m11) = 32 KB.
__device__ float4 g_M[N_HALF];

// ---------------------------------------------------------------------------
// Kernel 1: compose the 12 per-pair 2x2 matrices (trivial cost, 2048 threads).
// W layout: [LOG_N, N_HALF, 2, 2] row-major, 16B-aligned -> float4 loads.
// Per layer y = x @ W (y_j = sum_i x_i w_ij), so composite = W0*W1*...*W11
// multiplied left to right.
// ---------------------------------------------------------------------------
__global__ void compose_kernel(const float4* __restrict__ W4) {
    int p = blockIdx.x * blockDim.x + threadIdx.x;
    if (p >= N_HALF) return;

    float a00 = 1.f, a01 = 0.f, a10 = 0.f, a11 = 1.f;
#pragma unroll
    for (int l = 0; l < LOG_N; ++l) {
        float4 w = W4[(size_t)l * N_HALF + p];  // (w00,w01,w10,w11)
        float b00 = fmaf(a00, w.x, a01 * w.z);
        float b01 = fmaf(a00, w.y, a01 * w.w);
        float b10 = fmaf(a10, w.x, a11 * w.z);
        float b11 = fmaf(a10, w.y, a11 * w.w);
        a00 = b00; a01 = b01; a10 = b10; a11 = b11;
    }
    g_M[p] = make_float4(a00, a01, a10, a11);
}

// ---------------------------------------------------------------------------
// Kernel 2: apply. Each block stages all 2048 composite matrices (32 KB) in
// shared memory, then streams rows with float4 loads/stores. One float4 of x
// covers pairs (2i, 2i+1). Pure HBM-bound: 128 MB read + 128 MB write.
// ---------------------------------------------------------------------------
__global__ void __launch_bounds__(256) apply_kernel(const float* __restrict__ x,
                                                    float* __restrict__ y) {
    __shared__ float4 sM[N_HALF];  // 32 KB

    for (int i = threadIdx.x; i < N_HALF; i += blockDim.x)
        sM[i] = g_M[i];
    __syncthreads();

    const int f4_per_row = N_SIZE / 4;  // 1024

    for (int row = blockIdx.x; row < N_BATCH; row += gridDim.x) {
        const float4* __restrict__ xr = (const float4*)(x + (size_t)row * N_SIZE);
        float4* __restrict__ yr = (float4*)(y + (size_t)row * N_SIZE);

#pragma unroll 4
        for (int i = threadIdx.x; i < f4_per_row; i += blockDim.x) {
            float4 v  = xr[i];
            float4 m0 = sM[2 * i];
            float4 m1 = sM[2 * i + 1];
            float4 o;
            // y0 = x0*m00 + x1*m10 ; y1 = x0*m01 + x1*m11   (y = x @ M)
            o.x = fmaf(v.x, m0.x, v.y * m0.z);
            o.y = fmaf(v.x, m0.y, v.y * m0.w);
            o.z = fmaf(v.z, m1.x, v.w * m1.z);
            o.w = fmaf(v.z, m1.y, v.w * m1.w);
            yr[i] = o;
        }
    }
}

extern "C" void kernel_launch(void* const* d_in, const int* in_sizes, int n_in,
                              void* d_out, int out_size) {
    const float* x = (const float*)d_in[0];  // [8192, 4096] fp32
    const float* W = (const float*)d_in[1];  // [12, 2048, 2, 2] fp32
    float* out = (float*)d_out;

    compose_kernel<<<(N_HALF + 255) / 256, 256>>>((const float4*)W);

    // 592 blocks: each handles ~14 rows, amortizing the 32 KB smem fill (~7%
    // extra traffic) while keeping the full chip busy.
    apply_kernel<<<592, 256>>>(x, out);
}

// round 5
// speedup vs baseline: 1.0755x; 1.0755x over previous
#include <cuda_runtime.h>
#include <cuda_bf16.h>

// ButterflyTransform: 12 layers of adjacent-pair 2x2 butterflies over [8192, 4096].
// All layers pair the SAME adjacent elements (2p, 2p+1), so the whole network
// collapses to one composite 2x2 matrix per pair:
//   M_p = W0[p] @ W1[p] @ ... @ W11[p]
// applied in a single streaming pass: out[b,2p:2p+2] = x[b,2p:2p+2] @ M_p.
//
// R5: shared-memory M staging replaced with REGISTER-resident M. Each thread
// owns fixed column slots (tid + k*256, k=0..3) across all rows, so its 8
// composite matrices are loaded once into 32 registers. Eliminates all LDS
// traffic (L1 was 60% busy, throttling DRAM at 62%) and the 32KB smem fill.

#define N_SIZE   4096
#define N_HALF   2048
#define LOG_N    12
#define N_BATCH  8192

// Composite matrices: 2048 pairs x (m00,m01,m10,m11) = 32 KB.
__device__ float4 g_M[N_HALF];

// ---------------------------------------------------------------------------
// Kernel 1: compose the 12 per-pair 2x2 matrices (trivial cost, 2048 threads).
// W layout: [LOG_N, N_HALF, 2, 2] row-major, 16B-aligned -> float4 loads.
// Per layer y = x @ W (y_j = sum_i x_i w_ij): composite = W0*W1*...*W11.
// ---------------------------------------------------------------------------
__global__ void compose_kernel(const float4* __restrict__ W4) {
    int p = blockIdx.x * blockDim.x + threadIdx.x;
    if (p >= N_HALF) return;

    float a00 = 1.f, a01 = 0.f, a10 = 0.f, a11 = 1.f;
#pragma unroll
    for (int l = 0; l < LOG_N; ++l) {
        float4 w = W4[(size_t)l * N_HALF + p];  // (w00,w01,w10,w11)
        float b00 = fmaf(a00, w.x, a01 * w.z);
        float b01 = fmaf(a00, w.y, a01 * w.w);
        float b10 = fmaf(a10, w.x, a11 * w.z);
        float b11 = fmaf(a10, w.y, a11 * w.w);
        a00 = b00; a01 = b01; a10 = b10; a11 = b11;
    }
    g_M[p] = make_float4(a00, a01, a10, a11);
}

// ---------------------------------------------------------------------------
// Kernel 2: apply with register-resident M. Per row-iteration per thread:
// 4 independent LDG.128 + 16 FMA + 4 STG.128. No smem, no barriers.
// Streaming cache hints (x/y have zero reuse).
// ---------------------------------------------------------------------------
__global__ void __launch_bounds__(256) apply_kernel(const float* __restrict__ x,
                                                    float* __restrict__ y) {
    const int tid = threadIdx.x;

    // This thread's 8 composite matrices (columns tid + k*256), fixed for all rows.
    float4 mA[4], mB[4];
#pragma unroll
    for (int k = 0; k < 4; ++k) {
        int i = k * 256 + tid;          // float4-slot index within the row
        mA[k] = g_M[2 * i];
        mB[k] = g_M[2 * i + 1];
    }

    for (int row = blockIdx.x; row < N_BATCH; row += gridDim.x) {
        const float4* __restrict__ xr = (const float4*)(x + (size_t)row * N_SIZE);
        float4* __restrict__ yr = (float4*)(y + (size_t)row * N_SIZE);

        float4 v[4];
#pragma unroll
        for (int k = 0; k < 4; ++k)
            v[k] = __ldcs(&xr[k * 256 + tid]);   // 4 independent LDG.128 up front

#pragma unroll
        for (int k = 0; k < 4; ++k) {
            float4 o;
            // y0 = x0*m00 + x1*m10 ; y1 = x0*m01 + x1*m11   (y = x @ M)
            o.x = fmaf(v[k].x, mA[k].x, v[k].y * mA[k].z);
            o.y = fmaf(v[k].x, mA[k].y, v[k].y * mA[k].w);
            o.z = fmaf(v[k].z, mB[k].x, v[k].w * mB[k].z);
            o.w = fmaf(v[k].z, mB[k].y, v[k].w * mB[k].w);
            __stcs(&yr[k * 256 + tid], o);
        }
    }
}

extern "C" void kernel_launch(void* const* d_in, const int* in_sizes, int n_in,
                              void* d_out, int out_size) {
    const float* x = (const float*)d_in[0];  // [8192, 4096] fp32
    const float* W = (const float*)d_in[1];  // [12, 2048, 2, 2] fp32
    float* out = (float*)d_out;

    compose_kernel<<<(N_HALF + 255) / 256, 256>>>((const float4*)W);

    // No smem now -> 4 blocks/SM register-limited. 1184 = 148 SMs * 8 blocks;
    // each block streams ~7 rows.
    apply_kernel<<<1184, 256>>>(x, out);
}